// round 2
// baseline (speedup 1.0000x reference)
#include <cuda_runtime.h>
#include <math.h>

// Shapes: B=64, T_IN=12, HORIZON=12, N=512, H=64, TD=32, ED=16, DIN=1, DOUT=1,
// CHEB_K=3, D_HEADS=8.  BH = B*HORIZON = 768.
//
// Pipeline:
//  A  = softmax(relu(E E^T), rows)             -> stored transposed g_At[m][n]
//  QS/KP/VP : tiny TD-part projections of q/k/v
//  attention -> g_de (768,512,64)
//  Y1 = A@de ; Y2 = A@Y1
//  gcn1 GEMM (Xcat=[de|Y1|2Y2-de] @ W1[bh]) -> sigmoid -> g_rg, g_zde(=z*de)
//  Y1 = A@zde ; Y2 = A@Y1
//  gcn2 GEMM -> tanh -> state=rg*de+(1-rg)*hc -> out proj -> d_out

__device__ float g_At [512*512];
__device__ float g_QS [768*64];
__device__ float g_KP [64*64];
__device__ float g_VP [64*64];
__device__ float g_de [768*512*64];
__device__ float g_Y1 [768*512*64];
__device__ float g_Y2 [768*512*64];
__device__ float g_rg [768*512*64];
__device__ float g_zde[768*512*64];
__device__ float g_W1 [768*24960];   // 768 x (3*65*128)
__device__ float g_W2 [768*12480];   // 768 x (3*65*64)
__device__ float g_b1 [768*128];
__device__ float g_b2 [768*64];

__device__ __forceinline__ float* buf_sel(int s) {
    switch (s) {
        case 0: return g_de;  case 1: return g_Y1;  case 2: return g_Y2;
        case 3: return g_zde; case 4: return g_W1;  case 5: return g_W2;
        case 6: return g_b1;  default: return g_b2;
    }
}

// ---------------------------------------------------------------------------
// A^T: At[m][n] = softmax_row_n(relu(E E^T))[n][m].  One block per row n.
// ---------------------------------------------------------------------------
__global__ __launch_bounds__(128) void k_At(const float* __restrict__ E) {
    int n = blockIdx.x;
    int tid = threadIdx.x;
    __shared__ float En[16];
    __shared__ float sred[128];
    if (tid < 16) En[tid] = E[n * 16 + tid];
    __syncthreads();
    float r[4];
#pragma unroll
    for (int i = 0; i < 4; i++) {
        int m = tid + i * 128;
        float acc = 0.f;
#pragma unroll
        for (int d = 0; d < 16; d++) acc = fmaf(En[d], E[m * 16 + d], acc);
        r[i] = fmaxf(acc, 0.f);
    }
    float mx = fmaxf(fmaxf(r[0], r[1]), fmaxf(r[2], r[3]));
    sred[tid] = mx;
    __syncthreads();
    for (int s = 64; s > 0; s >>= 1) {
        if (tid < s) sred[tid] = fmaxf(sred[tid], sred[tid + s]);
        __syncthreads();
    }
    mx = sred[0];
    __syncthreads();
    float sum = 0.f;
#pragma unroll
    for (int i = 0; i < 4; i++) { r[i] = expf(r[i] - mx); sum += r[i]; }
    sred[tid] = sum;
    __syncthreads();
    for (int s = 64; s > 0; s >>= 1) {
        if (tid < s) sred[tid] += sred[tid + s];
        __syncthreads();
    }
    float inv = 1.f / sred[0];
#pragma unroll
    for (int i = 0; i < 4; i++)
        g_At[(size_t)(tid + i * 128) * 512 + n] = r[i] * inv;
}

// ---------------------------------------------------------------------------
// Per-batch weight mix: out[bh][j] = sum_d temb[bh][d]*wp[d][j] + wbase[j]
// grid: (ceil(ncol/256), 48) — 16 bh rows per block.
// ---------------------------------------------------------------------------
__global__ __launch_bounds__(256) void k_wmix(const float* __restrict__ temb,
                                              const float* __restrict__ wp,
                                              const float* __restrict__ wbase,
                                              int outsel, int ncol) {
    __shared__ float ts[16][32];
    int bh0 = blockIdx.y * 16;
    for (int i = threadIdx.x; i < 512; i += 256)
        ts[i >> 5][i & 31] = temb[bh0 * 32 + i];
    __syncthreads();
    int j = blockIdx.x * 256 + threadIdx.x;
    if (j >= ncol) return;
    float* out = buf_sel(outsel);
    float base = wbase[j];
    float acc[16];
#pragma unroll
    for (int r = 0; r < 16; r++) acc[r] = base;
    for (int d = 0; d < 32; d++) {
        float w = wp[(size_t)d * ncol + j];
#pragma unroll
        for (int r = 0; r < 16; r++) acc[r] = fmaf(ts[r][d], w, acc[r]);
    }
#pragma unroll
    for (int r = 0; r < 16; r++) out[(size_t)(bh0 + r) * ncol + j] = acc[r];
}

// ---------------------------------------------------------------------------
// QS[bh][h] = relu-pre part: ne2[bh]@Wq[:32] + bq      (768 blocks x 64 thr)
// ---------------------------------------------------------------------------
__global__ __launch_bounds__(64) void k_qs(const float* __restrict__ ne2,
                                           const float* __restrict__ Wq,
                                           const float* __restrict__ bq) {
    int h = threadIdx.x;
    int bh = blockIdx.x;
    float acc = bq[h];
#pragma unroll 8
    for (int d = 0; d < 32; d++) acc = fmaf(ne2[bh * 32 + d], Wq[d * 64 + h], acc);
    g_QS[bh * 64 + h] = acc;
}

// KP/VP from STE_P = ne1[:, 11, :].   64 blocks x 128 threads (K half, V half)
__global__ __launch_bounds__(128) void k_kpvp(const float* __restrict__ ne1,
                                              const float* __restrict__ Wk,
                                              const float* __restrict__ bk,
                                              const float* __restrict__ Wv,
                                              const float* __restrict__ bv) {
    int b = blockIdx.x;
    int t = threadIdx.x;
    int h = t & 63;
    bool isV = t >= 64;
    const float* W = isV ? Wv : Wk;
    const float* bb = isV ? bv : bk;
    float acc = bb[h];
#pragma unroll 8
    for (int d = 0; d < 32; d++)
        acc = fmaf(ne1[b * 384 + 352 + d], W[d * 64 + h], acc);
    if (isV) g_VP[b * 64 + h] = acc;
    else     g_KP[b * 64 + h] = acc;
}

// ---------------------------------------------------------------------------
// Attention + temporal-attention combine -> g_de[(b*12+t)][n][h]
// grid (128, 64), block (64, 4): thread = (h, n_local)
// ---------------------------------------------------------------------------
__global__ __launch_bounds__(256) void k_attn(const float* __restrict__ hN,
                                              const float* __restrict__ Wq,
                                              const float* __restrict__ Wk,
                                              const float* __restrict__ Wv,
                                              const float* __restrict__ taw,
                                              const float* __restrict__ tab) {
    int h = threadIdx.x;
    int nl = threadIdx.y;
    int n = blockIdx.x * 4 + nl;
    int b = blockIdx.y;
    __shared__ float Xs[4][64];
    __shared__ float Vs[4][64];
    __shared__ float Atn[4][12][8];
    float xh = hN[((size_t)b * 512 + n) * 64 + h];
    Xs[nl][h] = xh;
    __syncthreads();
    float xq = 0.f, xk = 0.f, xv = 0.f, xo = 0.f;
#pragma unroll 16
    for (int j = 0; j < 64; j++) {
        float xj = Xs[nl][j];
        xq = fmaf(xj, Wq[(32 + j) * 64 + h], xq);
        xk = fmaf(xj, Wk[(32 + j) * 64 + h], xk);
        xv = fmaf(xj, Wv[(32 + j) * 64 + h], xv);
        xo = fmaf(xj, taw[j * 64 + h], xo);   // ta_w[0][j][h]
    }
    float kv = fmaxf(g_KP[b * 64 + h] + xk, 0.f);
    float vv = fmaxf(g_VP[b * 64 + h] + xv, 0.f);
    Vs[nl][h] = vv;
    float lg[12];
#pragma unroll
    for (int t = 0; t < 12; t++) {
        float qv = fmaxf(g_QS[(b * 12 + t) * 64 + h] + xq, 0.f);
        float p = qv * kv;
        p += __shfl_xor_sync(0xffffffffu, p, 1);
        p += __shfl_xor_sync(0xffffffffu, p, 2);
        p += __shfl_xor_sync(0xffffffffu, p, 4);
        lg[t] = p;
    }
    float mx = lg[0];
#pragma unroll
    for (int t = 1; t < 12; t++) mx = fmaxf(mx, lg[t]);
    float s = 0.f;
#pragma unroll
    for (int t = 0; t < 12; t++) { lg[t] = expf(lg[t] - mx); s += lg[t]; }
    float inv = 1.f / s;
    if ((h & 7) == 0) {
#pragma unroll
        for (int t = 0; t < 12; t++) Atn[nl][t][h >> 3] = lg[t] * inv;
    }
    __syncthreads();
    float cd[8];
#pragma unroll
    for (int d = 0; d < 8; d++) cd[d] = 0.f;
#pragma unroll 16
    for (int j = 0; j < 64; j++)
        cd[j >> 3] = fmaf(Vs[nl][j], taw[(64 + j) * 64 + h], cd[j >> 3]); // ta_w[1]
    float base = xo + tab[h];
#pragma unroll
    for (int t = 0; t < 12; t++) {
        float acc = base;
#pragma unroll
        for (int d = 0; d < 8; d++) acc = fmaf(Atn[nl][t][d], cd[d], acc);
        g_de[((size_t)(b * 12 + t) * 512 + n) * 64 + h] = acc;
    }
}

// ---------------------------------------------------------------------------
// Y[bh][n][c] = sum_m At[m][n] * X[bh][m][c]     (M=512 n, N=64 c, K=512 m)
// grid (4, 768), 128 threads, 8x8 microtile in 4+4 splits (bank-conflict free)
// ---------------------------------------------------------------------------
__global__ __launch_bounds__(128) void k_gAx(int selX, int selY) {
    int bh = blockIdx.y;
    int n0 = blockIdx.x * 128;
    const float* Xb = buf_sel(selX) + (size_t)bh * 32768;
    float* Yb = buf_sel(selY) + (size_t)bh * 32768;
    __shared__ float As[16][128];
    __shared__ float Bs[16][64];
    int tid = threadIdx.x;
    int tx = tid & 7, ty = tid >> 3;
    float acc[2][2][4][4] = {};
    for (int k0 = 0; k0 < 512; k0 += 16) {
#pragma unroll
        for (int i = 0; i < 4; i++) {
            int idx = i * 512 + tid * 4;
            int kl = idx >> 7, nlo = idx & 127;
            *(float4*)&As[kl][nlo] =
                *(const float4*)&g_At[(size_t)(k0 + kl) * 512 + n0 + nlo];
        }
#pragma unroll
        for (int i = 0; i < 2; i++) {
            int idx = i * 512 + tid * 4;
            int kl = idx >> 6, cl = idx & 63;
            *(float4*)&Bs[kl][cl] = *(const float4*)&Xb[(k0 + kl) * 64 + cl];
        }
        __syncthreads();
#pragma unroll
        for (int kl = 0; kl < 16; kl++) {
            float a[2][4], bb[2][4];
            *(float4*)a[0] = *(float4*)&As[kl][ty * 4];
            *(float4*)a[1] = *(float4*)&As[kl][64 + ty * 4];
            *(float4*)bb[0] = *(float4*)&Bs[kl][tx * 4];
            *(float4*)bb[1] = *(float4*)&Bs[kl][32 + tx * 4];
#pragma unroll
            for (int rb = 0; rb < 2; rb++)
#pragma unroll
                for (int r = 0; r < 4; r++)
#pragma unroll
                    for (int cb = 0; cb < 2; cb++)
#pragma unroll
                        for (int c = 0; c < 4; c++)
                            acc[rb][cb][r][c] =
                                fmaf(a[rb][r], bb[cb][c], acc[rb][cb][r][c]);
        }
        __syncthreads();
    }
#pragma unroll
    for (int rb = 0; rb < 2; rb++)
#pragma unroll
        for (int r = 0; r < 4; r++) {
            int row = n0 + rb * 64 + ty * 4 + r;
#pragma unroll
            for (int cb = 0; cb < 2; cb++) {
                float4 v = make_float4(acc[rb][cb][r][0], acc[rb][cb][r][1],
                                       acc[rb][cb][r][2], acc[rb][cb][r][3]);
                *(float4*)&Yb[(size_t)row * 64 + cb * 32 + tx * 4] = v;
            }
        }
}

// ---------------------------------------------------------------------------
// gcn1: out = Xcat(512x192) @ W1[bh](192x128) + b1; sigmoid; emit rg, z*de.
// Xcat cols: [0,64)=de, [64,128)=Y1, [128,192)=2*Y2-de
// grid (4, 768), 256 threads, tile 128x128
// ---------------------------------------------------------------------------
__global__ __launch_bounds__(256) void k_gcn1() {
    int bh = blockIdx.y;
    int n0 = blockIdx.x * 128;
    const float* deb = g_de + (size_t)bh * 32768;
    const float* y1b = g_Y1 + (size_t)bh * 32768;
    const float* y2b = g_Y2 + (size_t)bh * 32768;
    const float* Wb = g_W1 + (size_t)bh * 24960;
    const float* bvp = g_b1 + bh * 128;
    __shared__ float As[16][132];
    __shared__ float Bs[16][128];
    int tid = threadIdx.x, tx = tid & 15, ty = tid >> 4;
    float acc[2][2][4][4] = {};
    for (int kc = 0; kc < 12; kc++) {
        int r0 = kc * 16, src = r0 >> 6, c0 = r0 & 63;
#pragma unroll
        for (int i = 0; i < 2; i++) {
            int idx = i * 1024 + tid * 4;
            int nlo = idx >> 4, cl = idx & 15;
            size_t g = (size_t)(n0 + nlo) * 64 + c0 + cl;
            float4 v;
            if (src == 0) v = *(const float4*)&deb[g];
            else if (src == 1) v = *(const float4*)&y1b[g];
            else {
                float4 a2 = *(const float4*)&y2b[g];
                float4 dd = *(const float4*)&deb[g];
                v = make_float4(2.f * a2.x - dd.x, 2.f * a2.y - dd.y,
                                2.f * a2.z - dd.z, 2.f * a2.w - dd.w);
            }
            As[cl + 0][nlo] = v.x; As[cl + 1][nlo] = v.y;
            As[cl + 2][nlo] = v.z; As[cl + 3][nlo] = v.w;
        }
#pragma unroll
        for (int i = 0; i < 2; i++) {
            int idx = i * 1024 + tid * 4;
            int kl = idx >> 7, ol = idx & 127;
            int r = r0 + kl;
            int gr = r + (r >> 6) + 1;       // skip the zero i=0 channel
            *(float4*)&Bs[kl][ol] = *(const float4*)&Wb[gr * 128 + ol];
        }
        __syncthreads();
#pragma unroll
        for (int kl = 0; kl < 16; kl++) {
            float a[2][4], bb[2][4];
            *(float4*)a[0] = *(float4*)&As[kl][ty * 4];
            *(float4*)a[1] = *(float4*)&As[kl][64 + ty * 4];
            *(float4*)bb[0] = *(float4*)&Bs[kl][tx * 4];
            *(float4*)bb[1] = *(float4*)&Bs[kl][64 + tx * 4];
#pragma unroll
            for (int rb = 0; rb < 2; rb++)
#pragma unroll
                for (int r = 0; r < 4; r++)
#pragma unroll
                    for (int cb = 0; cb < 2; cb++)
#pragma unroll
                        for (int c = 0; c < 4; c++)
                            acc[rb][cb][r][c] =
                                fmaf(a[rb][r], bb[cb][c], acc[rb][cb][r][c]);
        }
        __syncthreads();
    }
#pragma unroll
    for (int rb = 0; rb < 2; rb++)
#pragma unroll
        for (int r = 0; r < 4; r++) {
            int row = n0 + rb * 64 + ty * 4 + r;
#pragma unroll
            for (int cb = 0; cb < 2; cb++)
#pragma unroll
                for (int c = 0; c < 4; c++) {
                    int col = cb * 64 + tx * 4 + c;
                    float x = acc[rb][cb][r][c] + bvp[col];
                    float sg = 1.f / (1.f + expf(-x));
                    if (cb == 0)
                        g_zde[(size_t)bh * 32768 + row * 64 + col] =
                            sg * deb[row * 64 + col];
                    else
                        g_rg[(size_t)bh * 32768 + row * 64 + (col - 64)] = sg;
                }
        }
}

// ---------------------------------------------------------------------------
// gcn2 + GRU combine + output projection.  Xcat from (zde, Y1, Y2).
// grid (4, 768), 128 threads, tile 128x64.  Writes d_out directly.
// ---------------------------------------------------------------------------
__global__ __launch_bounds__(128) void k_gcn2(float* __restrict__ out,
                                              const float* __restrict__ ow,
                                              const float* __restrict__ ob) {
    int bh = blockIdx.y;
    int tt = bh % 12;
    int n0 = blockIdx.x * 128;
    const float* xb  = g_zde + (size_t)bh * 32768;
    const float* y1b = g_Y1 + (size_t)bh * 32768;
    const float* y2b = g_Y2 + (size_t)bh * 32768;
    const float* deb = g_de + (size_t)bh * 32768;
    const float* rgb = g_rg + (size_t)bh * 32768;
    const float* Wb = g_W2 + (size_t)bh * 12480;
    const float* bvp = g_b2 + bh * 64;
    __shared__ float As[16][132];
    __shared__ float Bs[16][64];
    int tid = threadIdx.x, tx = tid & 7, ty = tid >> 3;
    float acc[2][2][4][4] = {};
    for (int kc = 0; kc < 12; kc++) {
        int r0 = kc * 16, src = r0 >> 6, c0 = r0 & 63;
#pragma unroll
        for (int i = 0; i < 4; i++) {
            int idx = i * 512 + tid * 4;
            int nlo = idx >> 4, cl = idx & 15;
            size_t g = (size_t)(n0 + nlo) * 64 + c0 + cl;
            float4 v;
            if (src == 0) v = *(const float4*)&xb[g];
            else if (src == 1) v = *(const float4*)&y1b[g];
            else {
                float4 a2 = *(const float4*)&y2b[g];
                float4 dd = *(const float4*)&xb[g];
                v = make_float4(2.f * a2.x - dd.x, 2.f * a2.y - dd.y,
                                2.f * a2.z - dd.z, 2.f * a2.w - dd.w);
            }
            As[cl + 0][nlo] = v.x; As[cl + 1][nlo] = v.y;
            As[cl + 2][nlo] = v.z; As[cl + 3][nlo] = v.w;
        }
#pragma unroll
        for (int i = 0; i < 2; i++) {
            int idx = i * 512 + tid * 4;
            int kl = idx >> 6, ol = idx & 63;
            int r = r0 + kl;
            int gr = r + (r >> 6) + 1;
            *(float4*)&Bs[kl][ol] = *(const float4*)&Wb[gr * 64 + ol];
        }
        __syncthreads();
#pragma unroll
        for (int kl = 0; kl < 16; kl++) {
            float a[2][4], bb[2][4];
            *(float4*)a[0] = *(float4*)&As[kl][ty * 4];
            *(float4*)a[1] = *(float4*)&As[kl][64 + ty * 4];
            *(float4*)bb[0] = *(float4*)&Bs[kl][tx * 4];
            *(float4*)bb[1] = *(float4*)&Bs[kl][32 + tx * 4];
#pragma unroll
            for (int rb = 0; rb < 2; rb++)
#pragma unroll
                for (int r = 0; r < 4; r++)
#pragma unroll
                    for (int cb = 0; cb < 2; cb++)
#pragma unroll
                        for (int c = 0; c < 4; c++)
                            acc[rb][cb][r][c] =
                                fmaf(a[rb][r], bb[cb][c], acc[rb][cb][r][c]);
        }
        __syncthreads();
    }
#pragma unroll
    for (int rb = 0; rb < 2; rb++)
#pragma unroll
        for (int r = 0; r < 4; r++) {
            int row = n0 + rb * 64 + ty * 4 + r;
            float part = 0.f;
#pragma unroll
            for (int cb = 0; cb < 2; cb++)
#pragma unroll
                for (int c = 0; c < 4; c++) {
                    int col = cb * 32 + tx * 4 + c;
                    float gv = tanhf(acc[rb][cb][r][c] + bvp[col]);
                    float rgv = rgb[row * 64 + col];
                    float st = rgv * deb[row * 64 + col] + (1.f - rgv) * gv;
                    part = fmaf(st, ow[tt * 64 + col], part);
                }
            part += __shfl_xor_sync(0xffffffffu, part, 1);
            part += __shfl_xor_sync(0xffffffffu, part, 2);
            part += __shfl_xor_sync(0xffffffffu, part, 4);
            if (tx == 0) out[(size_t)bh * 512 + row] = part + ob[tt];
        }
}

// ---------------------------------------------------------------------------
extern "C" void kernel_launch(void* const* d_in, const int* in_sizes, int n_in,
                              void* d_out, int out_size) {
    (void)in_sizes; (void)n_in; (void)out_size;
    const float* hN  = (const float*)d_in[2];   // h_n (1,B,N,H)
    const float* ne1 = (const float*)d_in[3];   // (B,12,32)
    const float* ne2 = (const float*)d_in[4];   // (B,12,32) == temb (768,32)
    const float* E   = (const float*)d_in[5];   // (512,16)
    const float* Wq  = (const float*)d_in[6];
    const float* bq  = (const float*)d_in[7];
    const float* Wk  = (const float*)d_in[8];
    const float* bk  = (const float*)d_in[9];
    const float* Wv  = (const float*)d_in[10];
    const float* bv  = (const float*)d_in[11];
    const float* taw = (const float*)d_in[12];
    const float* tab = (const float*)d_in[13];
    const float* gwp = (const float*)d_in[14];
    const float* gw  = (const float*)d_in[15];
    const float* gbp = (const float*)d_in[16];
    const float* gb  = (const float*)d_in[17];
    const float* uwp = (const float*)d_in[18];
    const float* uw  = (const float*)d_in[19];
    const float* ubp = (const float*)d_in[20];
    const float* ub  = (const float*)d_in[21];
    const float* ow  = (const float*)d_in[22];  // (12,64,1)
    const float* ob  = (const float*)d_in[23];  // (12,1)
    float* out = (float*)d_out;

    k_At<<<512, 128>>>(E);
    k_wmix<<<dim3(98, 48), 256>>>(ne2, gwp, gw, 4, 24960);
    k_wmix<<<dim3(49, 48), 256>>>(ne2, uwp, uw, 5, 12480);
    k_wmix<<<dim3(1, 48), 256>>>(ne2, gbp, gb, 6, 128);
    k_wmix<<<dim3(1, 48), 256>>>(ne2, ubp, ub, 7, 64);
    k_qs<<<768, 64>>>(ne2, Wq, bq);
    k_kpvp<<<64, 128>>>(ne1, Wk, bk, Wv, bv);
    k_attn<<<dim3(128, 64), dim3(64, 4)>>>(hN, Wq, Wk, Wv, taw, tab);

    k_gAx<<<dim3(4, 768), 128>>>(0, 1);   // Y1 = A @ de
    k_gAx<<<dim3(4, 768), 128>>>(1, 2);   // Y2 = A @ Y1
    k_gcn1<<<dim3(4, 768), 256>>>();      // -> rg, zde
    k_gAx<<<dim3(4, 768), 128>>>(3, 1);   // Y1 = A @ zde
    k_gAx<<<dim3(4, 768), 128>>>(1, 2);   // Y2 = A @ Y1
    k_gcn2<<<dim3(4, 768), 128>>>(out, ow, ob);
}

// round 6
// speedup vs baseline: 1.4123x; 1.4123x over previous
#include <cuda_runtime.h>
#include <stdint.h>
#include <math.h>

// Shapes: B=64, T_IN=12, HORIZON=12, N=512, H=64, TD=32, ED=16, DIN=1, DOUT=1,
// CHEB_K=3, D_HEADS=8.  BH = B*HORIZON = 768.
//
// Pipeline:
//  A  = softmax(relu(E E^T), rows)             -> stored transposed g_At[m][n]
//  QS/KP/VP : tiny TD-part projections of q/k/v
//  attention -> g_de (768,512,64)
//  Y1 = A@de ; Y2 = A@Y1                       (tf32 mma.sync)
//  gcn1 GEMM (Xcat=[de|Y1|2Y2-de] @ W1[bh]) -> sigmoid -> g_rg, g_zde(=z*de)
//  Y1 = A@zde ; Y2 = A@Y1                      (tf32 mma.sync)
//  gcn2 GEMM -> tanh -> state=rg*de+(1-rg)*hc -> out proj -> d_out

__device__ float g_At [512*512];
__device__ float g_QS [768*64];
__device__ float g_KP [64*64];
__device__ float g_VP [64*64];
__device__ float g_de [768*512*64];
__device__ float g_Y1 [768*512*64];
__device__ float g_Y2 [768*512*64];
__device__ float g_rg [768*512*64];
__device__ float g_zde[768*512*64];
__device__ float g_W1 [768*24960];   // 768 x (3*65*128)
__device__ float g_W2 [768*12480];   // 768 x (3*65*64)
__device__ float g_b1 [768*128];
__device__ float g_b2 [768*64];

__device__ __forceinline__ float* buf_sel(int s) {
    switch (s) {
        case 0: return g_de;  case 1: return g_Y1;  case 2: return g_Y2;
        case 3: return g_zde; case 4: return g_W1;  case 5: return g_W2;
        case 6: return g_b1;  default: return g_b2;
    }
}

__device__ __forceinline__ uint32_t f2tf(float f) {
    uint32_t u;
    asm("cvt.rna.tf32.f32 %0, %1;" : "=r"(u) : "f"(f));
    return u;
}

__device__ __forceinline__ void mma_tf32(float4& d,
                                         uint32_t a0, uint32_t a1,
                                         uint32_t a2, uint32_t a3,
                                         uint32_t b0, uint32_t b1) {
    asm volatile(
        "mma.sync.aligned.m16n8k8.row.col.f32.tf32.tf32.f32 "
        "{%0,%1,%2,%3}, {%4,%5,%6,%7}, {%8,%9}, {%0,%1,%2,%3};\n"
        : "+f"(d.x), "+f"(d.y), "+f"(d.z), "+f"(d.w)
        : "r"(a0), "r"(a1), "r"(a2), "r"(a3), "r"(b0), "r"(b1));
}

// ---------------------------------------------------------------------------
// A^T: At[m][n] = softmax_row_n(relu(E E^T))[n][m].  One block per row n.
// ---------------------------------------------------------------------------
__global__ __launch_bounds__(128) void k_At(const float* __restrict__ E) {
    int n = blockIdx.x;
    int tid = threadIdx.x;
    __shared__ float En[16];
    __shared__ float sred[128];
    if (tid < 16) En[tid] = E[n * 16 + tid];
    __syncthreads();
    float r[4];
#pragma unroll
    for (int i = 0; i < 4; i++) {
        int m = tid + i * 128;
        float acc = 0.f;
#pragma unroll
        for (int d = 0; d < 16; d++) acc = fmaf(En[d], E[m * 16 + d], acc);
        r[i] = fmaxf(acc, 0.f);
    }
    float mx = fmaxf(fmaxf(r[0], r[1]), fmaxf(r[2], r[3]));
    sred[tid] = mx;
    __syncthreads();
    for (int s = 64; s > 0; s >>= 1) {
        if (tid < s) sred[tid] = fmaxf(sred[tid], sred[tid + s]);
        __syncthreads();
    }
    mx = sred[0];
    __syncthreads();
    float sum = 0.f;
#pragma unroll
    for (int i = 0; i < 4; i++) { r[i] = expf(r[i] - mx); sum += r[i]; }
    sred[tid] = sum;
    __syncthreads();
    for (int s = 64; s > 0; s >>= 1) {
        if (tid < s) sred[tid] += sred[tid + s];
        __syncthreads();
    }
    float inv = 1.f / sred[0];
#pragma unroll
    for (int i = 0; i < 4; i++)
        g_At[(size_t)(tid + i * 128) * 512 + n] = r[i] * inv;
}

// ---------------------------------------------------------------------------
// Per-batch weight mix: out[bh][j] = sum_d temb[bh][d]*wp[d][j] + wbase[j]
// ---------------------------------------------------------------------------
__global__ __launch_bounds__(256) void k_wmix(const float* __restrict__ temb,
                                              const float* __restrict__ wp,
                                              const float* __restrict__ wbase,
                                              int outsel, int ncol) {
    __shared__ float ts[16][32];
    int bh0 = blockIdx.y * 16;
    for (int i = threadIdx.x; i < 512; i += 256)
        ts[i >> 5][i & 31] = temb[bh0 * 32 + i];
    __syncthreads();
    int j = blockIdx.x * 256 + threadIdx.x;
    if (j >= ncol) return;
    float* out = buf_sel(outsel);
    float base = wbase[j];
    float acc[16];
#pragma unroll
    for (int r = 0; r < 16; r++) acc[r] = base;
    for (int d = 0; d < 32; d++) {
        float w = wp[(size_t)d * ncol + j];
#pragma unroll
        for (int r = 0; r < 16; r++) acc[r] = fmaf(ts[r][d], w, acc[r]);
    }
#pragma unroll
    for (int r = 0; r < 16; r++) out[(size_t)(bh0 + r) * ncol + j] = acc[r];
}

// ---------------------------------------------------------------------------
// QS[bh][h] = relu-pre part: ne2[bh]@Wq[:32] + bq      (768 blocks x 64 thr)
// ---------------------------------------------------------------------------
__global__ __launch_bounds__(64) void k_qs(const float* __restrict__ ne2,
                                           const float* __restrict__ Wq,
                                           const float* __restrict__ bq) {
    int h = threadIdx.x;
    int bh = blockIdx.x;
    float acc = bq[h];
#pragma unroll 8
    for (int d = 0; d < 32; d++) acc = fmaf(ne2[bh * 32 + d], Wq[d * 64 + h], acc);
    g_QS[bh * 64 + h] = acc;
}

// KP/VP from STE_P = ne1[:, 11, :].   64 blocks x 128 threads (K half, V half)
__global__ __launch_bounds__(128) void k_kpvp(const float* __restrict__ ne1,
                                              const float* __restrict__ Wk,
                                              const float* __restrict__ bk,
                                              const float* __restrict__ Wv,
                                              const float* __restrict__ bv) {
    int b = blockIdx.x;
    int t = threadIdx.x;
    int h = t & 63;
    bool isV = t >= 64;
    const float* W = isV ? Wv : Wk;
    const float* bb = isV ? bv : bk;
    float acc = bb[h];
#pragma unroll 8
    for (int d = 0; d < 32; d++)
        acc = fmaf(ne1[b * 384 + 352 + d], W[d * 64 + h], acc);
    if (isV) g_VP[b * 64 + h] = acc;
    else     g_KP[b * 64 + h] = acc;
}

// ---------------------------------------------------------------------------
// Attention + temporal-attention combine -> g_de[(b*12+t)][n][h]
// grid (128, 64), block (64, 4): thread = (h, n_local)
// ---------------------------------------------------------------------------
__global__ __launch_bounds__(256) void k_attn(const float* __restrict__ hN,
                                              const float* __restrict__ Wq,
                                              const float* __restrict__ Wk,
                                              const float* __restrict__ Wv,
                                              const float* __restrict__ taw,
                                              const float* __restrict__ tab) {
    int h = threadIdx.x;
    int nl = threadIdx.y;
    int n = blockIdx.x * 4 + nl;
    int b = blockIdx.y;
    __shared__ float Xs[4][64];
    __shared__ float Vs[4][64];
    __shared__ float Atn[4][12][8];
    float xh = hN[((size_t)b * 512 + n) * 64 + h];
    Xs[nl][h] = xh;
    __syncthreads();
    float xq = 0.f, xk = 0.f, xv = 0.f, xo = 0.f;
#pragma unroll 16
    for (int j = 0; j < 64; j++) {
        float xj = Xs[nl][j];
        xq = fmaf(xj, Wq[(32 + j) * 64 + h], xq);
        xk = fmaf(xj, Wk[(32 + j) * 64 + h], xk);
        xv = fmaf(xj, Wv[(32 + j) * 64 + h], xv);
        xo = fmaf(xj, taw[j * 64 + h], xo);   // ta_w[0][j][h]
    }
    float kv = fmaxf(g_KP[b * 64 + h] + xk, 0.f);
    float vv = fmaxf(g_VP[b * 64 + h] + xv, 0.f);
    Vs[nl][h] = vv;
    float lg[12];
#pragma unroll
    for (int t = 0; t < 12; t++) {
        float qv = fmaxf(g_QS[(b * 12 + t) * 64 + h] + xq, 0.f);
        float p = qv * kv;
        p += __shfl_xor_sync(0xffffffffu, p, 1);
        p += __shfl_xor_sync(0xffffffffu, p, 2);
        p += __shfl_xor_sync(0xffffffffu, p, 4);
        lg[t] = p;
    }
    float mx = lg[0];
#pragma unroll
    for (int t = 1; t < 12; t++) mx = fmaxf(mx, lg[t]);
    float s = 0.f;
#pragma unroll
    for (int t = 0; t < 12; t++) { lg[t] = expf(lg[t] - mx); s += lg[t]; }
    float inv = 1.f / s;
    if ((h & 7) == 0) {
#pragma unroll
        for (int t = 0; t < 12; t++) Atn[nl][t][h >> 3] = lg[t] * inv;
    }
    __syncthreads();
    float cd[8];
#pragma unroll
    for (int d = 0; d < 8; d++) cd[d] = 0.f;
#pragma unroll 16
    for (int j = 0; j < 64; j++)
        cd[j >> 3] = fmaf(Vs[nl][j], taw[(64 + j) * 64 + h], cd[j >> 3]); // ta_w[1]
    float base = xo + tab[h];
#pragma unroll
    for (int t = 0; t < 12; t++) {
        float acc = base;
#pragma unroll
        for (int d = 0; d < 8; d++) acc = fmaf(Atn[nl][t][d], cd[d], acc);
        g_de[((size_t)(b * 12 + t) * 512 + n) * 64 + h] = acc;
    }
}

// ---------------------------------------------------------------------------
// Y[bh][n][c] = sum_m At[m][n] * X[bh][m][c]   via tf32 mma.sync m16n8k8.
// grid (4, 768), 128 threads (4 warps). Block tile 128(n) x 64(c), K=512.
// Warp tile 32x64 = 2 Mtiles x 8 Ntiles of m16n8.
// k-permutation: thread's two k-slots hold physical k {2t, 2t+1} so every
// fragment is one 8B LDS from [row][k]-major smem (pad 22, aligned).
// ---------------------------------------------------------------------------
__global__ __launch_bounds__(128) void k_gAx(int selX, int selY) {
    int bh = blockIdx.y;
    int n0 = blockIdx.x * 128;
    const float* Xb = buf_sel(selX) + (size_t)bh * 32768;
    float* Yb = buf_sel(selY) + (size_t)bh * 32768;
    __shared__ uint32_t As[128][22];   // [n][k] tf32 (k-chunk 16)
    __shared__ uint32_t Bs[64][22];    // [c][k] tf32
    int tid = threadIdx.x;
    int warp = tid >> 5, lane = tid & 31;
    int g = lane >> 2, t = lane & 3;
    int nw = warp * 32;
    float4 acc[2][8];
#pragma unroll
    for (int m = 0; m < 2; m++)
#pragma unroll
        for (int nt = 0; nt < 8; nt++)
            acc[m][nt] = make_float4(0.f, 0.f, 0.f, 0.f);

    for (int k0 = 0; k0 < 512; k0 += 16) {
#pragma unroll
        for (int kl = 0; kl < 16; kl++)
            As[tid][kl] = f2tf(g_At[(size_t)(k0 + kl) * 512 + n0 + tid]);
#pragma unroll
        for (int i = 0; i < 8; i++) {
            int idx = i * 128 + tid;
            int kl = idx >> 6, c = idx & 63;
            Bs[c][kl] = f2tf(Xb[(k0 + kl) * 64 + c]);
        }
        __syncthreads();
#pragma unroll
        for (int kk = 0; kk < 16; kk += 8) {
            uint2 al[2], ah[2];
#pragma unroll
            for (int m = 0; m < 2; m++) {
                al[m] = *(uint2*)&As[nw + m * 16 + g][kk + 2 * t];
                ah[m] = *(uint2*)&As[nw + m * 16 + 8 + g][kk + 2 * t];
            }
#pragma unroll
            for (int nt = 0; nt < 8; nt++) {
                uint2 b = *(uint2*)&Bs[nt * 8 + g][kk + 2 * t];
#pragma unroll
                for (int m = 0; m < 2; m++)
                    mma_tf32(acc[m][nt], al[m].x, ah[m].x, al[m].y, ah[m].y,
                             b.x, b.y);
            }
        }
        __syncthreads();
    }
#pragma unroll
    for (int m = 0; m < 2; m++) {
        int row = n0 + nw + m * 16 + g;
#pragma unroll
        for (int nt = 0; nt < 8; nt++) {
            int col = nt * 8 + 2 * t;
            *(float2*)&Yb[(size_t)row * 64 + col] =
                make_float2(acc[m][nt].x, acc[m][nt].y);
            *(float2*)&Yb[(size_t)(row + 8) * 64 + col] =
                make_float2(acc[m][nt].z, acc[m][nt].w);
        }
    }
}

// ---------------------------------------------------------------------------
// gcn1: out = Xcat(512x192) @ W1[bh](192x128) + b1; sigmoid; emit rg, z*de.
// Xcat cols: [0,64)=de, [64,128)=Y1, [128,192)=2*Y2-de
// grid (4, 768), 256 threads, tile 128x128
// ---------------------------------------------------------------------------
__global__ __launch_bounds__(256) void k_gcn1() {
    int bh = blockIdx.y;
    int n0 = blockIdx.x * 128;
    const float* deb = g_de + (size_t)bh * 32768;
    const float* y1b = g_Y1 + (size_t)bh * 32768;
    const float* y2b = g_Y2 + (size_t)bh * 32768;
    const float* Wb = g_W1 + (size_t)bh * 24960;
    const float* bvp = g_b1 + bh * 128;
    __shared__ float As[16][132];
    __shared__ float Bs[16][128];
    int tid = threadIdx.x, tx = tid & 15, ty = tid >> 4;
    float acc[2][2][4][4] = {};
    for (int kc = 0; kc < 12; kc++) {
        int r0 = kc * 16, src = r0 >> 6, c0 = r0 & 63;
#pragma unroll
        for (int i = 0; i < 2; i++) {
            int idx = i * 1024 + tid * 4;
            int nlo = idx >> 4, cl = idx & 15;
            size_t g = (size_t)(n0 + nlo) * 64 + c0 + cl;
            float4 v;
            if (src == 0) v = *(const float4*)&deb[g];
            else if (src == 1) v = *(const float4*)&y1b[g];
            else {
                float4 a2 = *(const float4*)&y2b[g];
                float4 dd = *(const float4*)&deb[g];
                v = make_float4(2.f * a2.x - dd.x, 2.f * a2.y - dd.y,
                                2.f * a2.z - dd.z, 2.f * a2.w - dd.w);
            }
            As[cl + 0][nlo] = v.x; As[cl + 1][nlo] = v.y;
            As[cl + 2][nlo] = v.z; As[cl + 3][nlo] = v.w;
        }
#pragma unroll
        for (int i = 0; i < 2; i++) {
            int idx = i * 1024 + tid * 4;
            int kl = idx >> 7, ol = idx & 127;
            int r = r0 + kl;
            int gr = r + (r >> 6) + 1;       // skip the zero i=0 channel
            *(float4*)&Bs[kl][ol] = *(const float4*)&Wb[gr * 128 + ol];
        }
        __syncthreads();
#pragma unroll
        for (int kl = 0; kl < 16; kl++) {
            float a[2][4], bb[2][4];
            *(float4*)a[0] = *(float4*)&As[kl][ty * 4];
            *(float4*)a[1] = *(float4*)&As[kl][64 + ty * 4];
            *(float4*)bb[0] = *(float4*)&Bs[kl][tx * 4];
            *(float4*)bb[1] = *(float4*)&Bs[kl][64 + tx * 4];
#pragma unroll
            for (int rb = 0; rb < 2; rb++)
#pragma unroll
                for (int r = 0; r < 4; r++)
#pragma unroll
                    for (int cb = 0; cb < 2; cb++)
#pragma unroll
                        for (int c = 0; c < 4; c++)
                            acc[rb][cb][r][c] =
                                fmaf(a[rb][r], bb[cb][c], acc[rb][cb][r][c]);
        }
        __syncthreads();
    }
#pragma unroll
    for (int rb = 0; rb < 2; rb++)
#pragma unroll
        for (int r = 0; r < 4; r++) {
            int row = n0 + rb * 64 + ty * 4 + r;
#pragma unroll
            for (int cb = 0; cb < 2; cb++)
#pragma unroll
                for (int c = 0; c < 4; c++) {
                    int col = cb * 64 + tx * 4 + c;
                    float x = acc[rb][cb][r][c] + bvp[col];
                    float sg = 1.f / (1.f + expf(-x));
                    if (cb == 0)
                        g_zde[(size_t)bh * 32768 + row * 64 + col] =
                            sg * deb[row * 64 + col];
                    else
                        g_rg[(size_t)bh * 32768 + row * 64 + (col - 64)] = sg;
                }
        }
}

// ---------------------------------------------------------------------------
// gcn2 + GRU combine + output projection.  Xcat from (zde, Y1, Y2).
// grid (4, 768), 128 threads, tile 128x64.  Writes d_out directly.
// ---------------------------------------------------------------------------
__global__ __launch_bounds__(128) void k_gcn2(float* __restrict__ out,
                                              const float* __restrict__ ow,
                                              const float* __restrict__ ob) {
    int bh = blockIdx.y;
    int tt = bh % 12;
    int n0 = blockIdx.x * 128;
    const float* xb  = g_zde + (size_t)bh * 32768;
    const float* y1b = g_Y1 + (size_t)bh * 32768;
    const float* y2b = g_Y2 + (size_t)bh * 32768;
    const float* deb = g_de + (size_t)bh * 32768;
    const float* rgb = g_rg + (size_t)bh * 32768;
    const float* Wb = g_W2 + (size_t)bh * 12480;
    const float* bvp = g_b2 + bh * 64;
    __shared__ float As[16][132];
    __shared__ float Bs[16][64];
    int tid = threadIdx.x, tx = tid & 7, ty = tid >> 3;
    float acc[2][2][4][4] = {};
    for (int kc = 0; kc < 12; kc++) {
        int r0 = kc * 16, src = r0 >> 6, c0 = r0 & 63;
#pragma unroll
        for (int i = 0; i < 4; i++) {
            int idx = i * 512 + tid * 4;
            int nlo = idx >> 4, cl = idx & 15;
            size_t g = (size_t)(n0 + nlo) * 64 + c0 + cl;
            float4 v;
            if (src == 0) v = *(const float4*)&xb[g];
            else if (src == 1) v = *(const float4*)&y1b[g];
            else {
                float4 a2 = *(const float4*)&y2b[g];
                float4 dd = *(const float4*)&xb[g];
                v = make_float4(2.f * a2.x - dd.x, 2.f * a2.y - dd.y,
                                2.f * a2.z - dd.z, 2.f * a2.w - dd.w);
            }
            As[cl + 0][nlo] = v.x; As[cl + 1][nlo] = v.y;
            As[cl + 2][nlo] = v.z; As[cl + 3][nlo] = v.w;
        }
#pragma unroll
        for (int i = 0; i < 2; i++) {
            int idx = i * 512 + tid * 4;
            int kl = idx >> 6, ol = idx & 63;
            int r = r0 + kl;
            int gr = r + (r >> 6) + 1;
            *(float4*)&Bs[kl][ol] = *(const float4*)&Wb[gr * 64 + ol];
        }
        __syncthreads();
#pragma unroll
        for (int kl = 0; kl < 16; kl++) {
            float a[2][4], bb[2][4];
            *(float4*)a[0] = *(float4*)&As[kl][ty * 4];
            *(float4*)a[1] = *(float4*)&As[kl][64 + ty * 4];
            *(float4*)bb[0] = *(float4*)&Bs[kl][tx * 4];
            *(float4*)bb[1] = *(float4*)&Bs[kl][32 + tx * 4];
#pragma unroll
            for (int rb = 0; rb < 2; rb++)
#pragma unroll
                for (int r = 0; r < 4; r++)
#pragma unroll
                    for (int cb = 0; cb < 2; cb++)
#pragma unroll
                        for (int c = 0; c < 4; c++)
                            acc[rb][cb][r][c] =
                                fmaf(a[rb][r], bb[cb][c], acc[rb][cb][r][c]);
        }
        __syncthreads();
    }
#pragma unroll
    for (int rb = 0; rb < 2; rb++)
#pragma unroll
        for (int r = 0; r < 4; r++) {
            int row = n0 + rb * 64 + ty * 4 + r;
            float part = 0.f;
#pragma unroll
            for (int cb = 0; cb < 2; cb++)
#pragma unroll
                for (int c = 0; c < 4; c++) {
                    int col = cb * 32 + tx * 4 + c;
                    float gv = tanhf(acc[rb][cb][r][c] + bvp[col]);
                    float rgv = rgb[row * 64 + col];
                    float st = rgv * deb[row * 64 + col] + (1.f - rgv) * gv;
                    part = fmaf(st, ow[tt * 64 + col], part);
                }
            part += __shfl_xor_sync(0xffffffffu, part, 1);
            part += __shfl_xor_sync(0xffffffffu, part, 2);
            part += __shfl_xor_sync(0xffffffffu, part, 4);
            if (tx == 0) out[(size_t)bh * 512 + row] = part + ob[tt];
        }
}

// ---------------------------------------------------------------------------
extern "C" void kernel_launch(void* const* d_in, const int* in_sizes, int n_in,
                              void* d_out, int out_size) {
    (void)in_sizes; (void)n_in; (void)out_size;
    const float* hN  = (const float*)d_in[2];   // h_n (1,B,N,H)
    const float* ne1 = (const float*)d_in[3];   // (B,12,32)
    const float* ne2 = (const float*)d_in[4];   // (B,12,32) == temb (768,32)
    const float* E   = (const float*)d_in[5];   // (512,16)
    const float* Wq  = (const float*)d_in[6];
    const float* bq  = (const float*)d_in[7];
    const float* Wk  = (const float*)d_in[8];
    const float* bk  = (const float*)d_in[9];
    const float* Wv  = (const float*)d_in[10];
    const float* bv  = (const float*)d_in[11];
    const float* taw = (const float*)d_in[12];
    const float* tab = (const float*)d_in[13];
    const float* gwp = (const float*)d_in[14];
    const float* gw  = (const float*)d_in[15];
    const float* gbp = (const float*)d_in[16];
    const float* gb  = (const float*)d_in[17];
    const float* uwp = (const float*)d_in[18];
    const float* uw  = (const float*)d_in[19];
    const float* ubp = (const float*)d_in[20];
    const float* ub  = (const float*)d_in[21];
    const float* ow  = (const float*)d_in[22];  // (12,64,1)
    const float* ob  = (const float*)d_in[23];  // (12,1)
    float* out = (float*)d_out;

    k_At<<<512, 128>>>(E);
    k_wmix<<<dim3(98, 48), 256>>>(ne2, gwp, gw, 4, 24960);
    k_wmix<<<dim3(49, 48), 256>>>(ne2, uwp, uw, 5, 12480);
    k_wmix<<<dim3(1, 48), 256>>>(ne2, gbp, gb, 6, 128);
    k_wmix<<<dim3(1, 48), 256>>>(ne2, ubp, ub, 7, 64);
    k_qs<<<768, 64>>>(ne2, Wq, bq);
    k_kpvp<<<64, 128>>>(ne1, Wk, bk, Wv, bv);
    k_attn<<<dim3(128, 64), dim3(64, 4)>>>(hN, Wq, Wk, Wv, taw, tab);

    k_gAx<<<dim3(4, 768), 128>>>(0, 1);   // Y1 = A @ de
    k_gAx<<<dim3(4, 768), 128>>>(1, 2);   // Y2 = A @ Y1
    k_gcn1<<<dim3(4, 768), 256>>>();      // -> rg, zde
    k_gAx<<<dim3(4, 768), 128>>>(3, 1);   // Y1 = A @ zde
    k_gAx<<<dim3(4, 768), 128>>>(1, 2);   // Y2 = A @ Y1
    k_gcn2<<<dim3(4, 768), 128>>>(out, ow, ob);
}

// round 7
// speedup vs baseline: 1.4279x; 1.0110x over previous
#include <cuda_runtime.h>
#include <stdint.h>
#include <math.h>

// Shapes: B=64, T_IN=12, HORIZON=12, N=512, H=64, TD=32, ED=16, DIN=1, DOUT=1,
// CHEB_K=3, D_HEADS=8.  BH = B*HORIZON = 768.
//
// Pipeline:
//  A  = softmax(relu(E E^T))          -> g_At[m][n] (transposed)
//  A2 = A@A                           -> g_A2t = At@At
//  attention -> g_de (768,512,64)
//  {Y1,Y2} = {A,A2} @ de              (one fused tf32 kernel)
//  gcn1 tf32 GEMM -> sigmoid -> g_rg, g_zde(=z*de)
//  {Y1,Y2} = {A,A2} @ zde
//  gcn2 tf32 GEMM -> tanh -> GRU -> out proj -> d_out

__device__ float g_At [512*512];
__device__ float g_A2t[512*512];
__device__ float g_QS [768*64];
__device__ float g_KP [64*64];
__device__ float g_VP [64*64];
__device__ float g_de [768*512*64];
__device__ float g_Y1 [768*512*64];
__device__ float g_Y2 [768*512*64];
__device__ float g_rg [768*512*64];
__device__ float g_zde[768*512*64];
__device__ float g_W1 [768*24960];   // 768 x (3*65*128)
__device__ float g_W2 [768*12480];   // 768 x (3*65*64)
__device__ float g_b1 [768*128];
__device__ float g_b2 [768*64];

__device__ __forceinline__ float* buf_sel(int s) {
    switch (s) {
        case 0: return g_de;  case 1: return g_Y1;  case 2: return g_Y2;
        case 3: return g_zde; case 4: return g_W1;  case 5: return g_W2;
        case 6: return g_b1;  default: return g_b2;
    }
}

__device__ __forceinline__ uint32_t f2tf(float f) {
    uint32_t u;
    asm("cvt.rna.tf32.f32 %0, %1;" : "=r"(u) : "f"(f));
    return u;
}

__device__ __forceinline__ void mma_tf32(float4& d,
                                         uint32_t a0, uint32_t a1,
                                         uint32_t a2, uint32_t a3,
                                         uint32_t b0, uint32_t b1) {
    asm volatile(
        "mma.sync.aligned.m16n8k8.row.col.f32.tf32.tf32.f32 "
        "{%0,%1,%2,%3}, {%4,%5,%6,%7}, {%8,%9}, {%0,%1,%2,%3};\n"
        : "+f"(d.x), "+f"(d.y), "+f"(d.z), "+f"(d.w)
        : "r"(a0), "r"(a1), "r"(a2), "r"(a3), "r"(b0), "r"(b1));
}

// ---------------------------------------------------------------------------
// A^T: At[m][n] = softmax_row_n(relu(E E^T))[n][m].  One block per row n.
// ---------------------------------------------------------------------------
__global__ __launch_bounds__(128) void k_At(const float* __restrict__ E) {
    int n = blockIdx.x;
    int tid = threadIdx.x;
    __shared__ float En[16];
    __shared__ float sred[128];
    if (tid < 16) En[tid] = E[n * 16 + tid];
    __syncthreads();
    float r[4];
#pragma unroll
    for (int i = 0; i < 4; i++) {
        int m = tid + i * 128;
        float acc = 0.f;
#pragma unroll
        for (int d = 0; d < 16; d++) acc = fmaf(En[d], E[m * 16 + d], acc);
        r[i] = fmaxf(acc, 0.f);
    }
    float mx = fmaxf(fmaxf(r[0], r[1]), fmaxf(r[2], r[3]));
    sred[tid] = mx;
    __syncthreads();
    for (int s = 64; s > 0; s >>= 1) {
        if (tid < s) sred[tid] = fmaxf(sred[tid], sred[tid + s]);
        __syncthreads();
    }
    mx = sred[0];
    __syncthreads();
    float sum = 0.f;
#pragma unroll
    for (int i = 0; i < 4; i++) { r[i] = expf(r[i] - mx); sum += r[i]; }
    sred[tid] = sum;
    __syncthreads();
    for (int s = 64; s > 0; s >>= 1) {
        if (tid < s) sred[tid] += sred[tid + s];
        __syncthreads();
    }
    float inv = 1.f / sred[0];
#pragma unroll
    for (int i = 0; i < 4; i++)
        g_At[(size_t)(tid + i * 128) * 512 + n] = r[i] * inv;
}

// ---------------------------------------------------------------------------
// A2t = At @ At  (fp32 SIMT tiled GEMM, 512^3, trivial cost)
// grid (4,4), 256 threads, tile 128x128, 8x8 micro
// ---------------------------------------------------------------------------
__global__ __launch_bounds__(256) void k_A2() {
    int nn0 = blockIdx.x * 128, m0 = blockIdx.y * 128;
    __shared__ float As[16][132];
    __shared__ float Bs[16][132];
    int tid = threadIdx.x, tx = tid & 15, ty = tid >> 4;
    float acc[8][8] = {};
    for (int k0 = 0; k0 < 512; k0 += 16) {
#pragma unroll
        for (int i = 0; i < 2; i++) {
            int idx = i * 1024 + tid * 4;
            int r = idx >> 4, kl = idx & 15;
            float4 v = *(const float4*)&g_At[(size_t)(m0 + r) * 512 + k0 + kl];
            As[kl + 0][r] = v.x; As[kl + 1][r] = v.y;
            As[kl + 2][r] = v.z; As[kl + 3][r] = v.w;
        }
#pragma unroll
        for (int i = 0; i < 2; i++) {
            int idx = i * 1024 + tid * 4;
            int kl = idx >> 7, nc = idx & 127;
            *(float4*)&Bs[kl][nc] =
                *(const float4*)&g_At[(size_t)(k0 + kl) * 512 + nn0 + nc];
        }
        __syncthreads();
#pragma unroll
        for (int kl = 0; kl < 16; kl++) {
            float a[8], b[8];
            *(float4*)&a[0] = *(float4*)&As[kl][ty * 8];
            *(float4*)&a[4] = *(float4*)&As[kl][ty * 8 + 4];
            *(float4*)&b[0] = *(float4*)&Bs[kl][tx * 8];
            *(float4*)&b[4] = *(float4*)&Bs[kl][tx * 8 + 4];
#pragma unroll
            for (int r = 0; r < 8; r++)
#pragma unroll
                for (int c = 0; c < 8; c++)
                    acc[r][c] = fmaf(a[r], b[c], acc[r][c]);
        }
        __syncthreads();
    }
#pragma unroll
    for (int r = 0; r < 8; r++)
#pragma unroll
        for (int c = 0; c < 8; c += 4)
            *(float4*)&g_A2t[(size_t)(m0 + ty * 8 + r) * 512 + nn0 + tx * 8 + c] =
                make_float4(acc[r][c], acc[r][c + 1], acc[r][c + 2], acc[r][c + 3]);
}

// ---------------------------------------------------------------------------
// Per-batch weight mix: out[bh][j] = sum_d temb[bh][d]*wp[d][j] + wbase[j]
// ---------------------------------------------------------------------------
__global__ __launch_bounds__(256) void k_wmix(const float* __restrict__ temb,
                                              const float* __restrict__ wp,
                                              const float* __restrict__ wbase,
                                              int outsel, int ncol) {
    __shared__ float ts[16][32];
    int bh0 = blockIdx.y * 16;
    for (int i = threadIdx.x; i < 512; i += 256)
        ts[i >> 5][i & 31] = temb[bh0 * 32 + i];
    __syncthreads();
    int j = blockIdx.x * 256 + threadIdx.x;
    if (j >= ncol) return;
    float* out = buf_sel(outsel);
    float base = wbase[j];
    float acc[16];
#pragma unroll
    for (int r = 0; r < 16; r++) acc[r] = base;
    for (int d = 0; d < 32; d++) {
        float w = wp[(size_t)d * ncol + j];
#pragma unroll
        for (int r = 0; r < 16; r++) acc[r] = fmaf(ts[r][d], w, acc[r]);
    }
#pragma unroll
    for (int r = 0; r < 16; r++) out[(size_t)(bh0 + r) * ncol + j] = acc[r];
}

// ---------------------------------------------------------------------------
// QS[bh][h] = ne2[bh]@Wq[:32] + bq
// ---------------------------------------------------------------------------
__global__ __launch_bounds__(64) void k_qs(const float* __restrict__ ne2,
                                           const float* __restrict__ Wq,
                                           const float* __restrict__ bq) {
    int h = threadIdx.x;
    int bh = blockIdx.x;
    float acc = bq[h];
#pragma unroll 8
    for (int d = 0; d < 32; d++) acc = fmaf(ne2[bh * 32 + d], Wq[d * 64 + h], acc);
    g_QS[bh * 64 + h] = acc;
}

__global__ __launch_bounds__(128) void k_kpvp(const float* __restrict__ ne1,
                                              const float* __restrict__ Wk,
                                              const float* __restrict__ bk,
                                              const float* __restrict__ Wv,
                                              const float* __restrict__ bv) {
    int b = blockIdx.x;
    int t = threadIdx.x;
    int h = t & 63;
    bool isV = t >= 64;
    const float* W = isV ? Wv : Wk;
    const float* bb = isV ? bv : bk;
    float acc = bb[h];
#pragma unroll 8
    for (int d = 0; d < 32; d++)
        acc = fmaf(ne1[b * 384 + 352 + d], W[d * 64 + h], acc);
    if (isV) g_VP[b * 64 + h] = acc;
    else     g_KP[b * 64 + h] = acc;
}

// ---------------------------------------------------------------------------
// Attention + temporal-attention combine -> g_de[(b*12+t)][n][h]
// ---------------------------------------------------------------------------
__global__ __launch_bounds__(256) void k_attn(const float* __restrict__ hN,
                                              const float* __restrict__ Wq,
                                              const float* __restrict__ Wk,
                                              const float* __restrict__ Wv,
                                              const float* __restrict__ taw,
                                              const float* __restrict__ tab) {
    int h = threadIdx.x;
    int nl = threadIdx.y;
    int n = blockIdx.x * 4 + nl;
    int b = blockIdx.y;
    __shared__ float Xs[4][64];
    __shared__ float Vs[4][64];
    __shared__ float Atn[4][12][8];
    float xh = hN[((size_t)b * 512 + n) * 64 + h];
    Xs[nl][h] = xh;
    __syncthreads();
    float xq = 0.f, xk = 0.f, xv = 0.f, xo = 0.f;
#pragma unroll 16
    for (int j = 0; j < 64; j++) {
        float xj = Xs[nl][j];
        xq = fmaf(xj, Wq[(32 + j) * 64 + h], xq);
        xk = fmaf(xj, Wk[(32 + j) * 64 + h], xk);
        xv = fmaf(xj, Wv[(32 + j) * 64 + h], xv);
        xo = fmaf(xj, taw[j * 64 + h], xo);
    }
    float kv = fmaxf(g_KP[b * 64 + h] + xk, 0.f);
    float vv = fmaxf(g_VP[b * 64 + h] + xv, 0.f);
    Vs[nl][h] = vv;
    float lg[12];
#pragma unroll
    for (int t = 0; t < 12; t++) {
        float qv = fmaxf(g_QS[(b * 12 + t) * 64 + h] + xq, 0.f);
        float p = qv * kv;
        p += __shfl_xor_sync(0xffffffffu, p, 1);
        p += __shfl_xor_sync(0xffffffffu, p, 2);
        p += __shfl_xor_sync(0xffffffffu, p, 4);
        lg[t] = p;
    }
    float mx = lg[0];
#pragma unroll
    for (int t = 1; t < 12; t++) mx = fmaxf(mx, lg[t]);
    float s = 0.f;
#pragma unroll
    for (int t = 0; t < 12; t++) { lg[t] = expf(lg[t] - mx); s += lg[t]; }
    float inv = 1.f / s;
    if ((h & 7) == 0) {
#pragma unroll
        for (int t = 0; t < 12; t++) Atn[nl][t][h >> 3] = lg[t] * inv;
    }
    __syncthreads();
    float cd[8];
#pragma unroll
    for (int d = 0; d < 8; d++) cd[d] = 0.f;
#pragma unroll 16
    for (int j = 0; j < 64; j++)
        cd[j >> 3] = fmaf(Vs[nl][j], taw[(64 + j) * 64 + h], cd[j >> 3]);
    float base = xo + tab[h];
#pragma unroll
    for (int t = 0; t < 12; t++) {
        float acc = base;
#pragma unroll
        for (int d = 0; d < 8; d++) acc = fmaf(Atn[nl][t][d], cd[d], acc);
        g_de[((size_t)(b * 12 + t) * 512 + n) * 64 + h] = acc;
    }
}

// ---------------------------------------------------------------------------
// Fused: Y1[bh] = A @ X[bh],  Y2[bh] = A2 @ X[bh]    (tf32 mma)
// grid (4, 768), 256 threads (8 warps): warps 0-3 -> A/Y1, warps 4-7 -> A2/Y2.
// Per warp: 32 rows x 64 cols = 2 Mtiles x 8 Ntiles of m16n8k8, K=512.
// ---------------------------------------------------------------------------
__global__ __launch_bounds__(256) void k_gAx2(int selX) {
    int bh = blockIdx.y;
    int n0 = blockIdx.x * 128;
    const float* Xb = buf_sel(selX) + (size_t)bh * 32768;
    __shared__ uint32_t As[2][128][20];
    __shared__ uint32_t Bs[64][20];
    int tid = threadIdx.x;
    int warp = tid >> 5, lane = tid & 31;
    int mat = warp >> 2, w4 = warp & 3;
    int g = lane >> 2, t = lane & 3;
    int nw = w4 * 32;
    float* Yb = (mat ? g_Y2 : g_Y1) + (size_t)bh * 32768;
    float4 acc[2][8];
#pragma unroll
    for (int m = 0; m < 2; m++)
#pragma unroll
        for (int nt = 0; nt < 8; nt++)
            acc[m][nt] = make_float4(0.f, 0.f, 0.f, 0.f);

    int lm = tid >> 7, lcol = tid & 127;
    const float* Asrc = lm ? g_A2t : g_At;
    for (int k0 = 0; k0 < 512; k0 += 16) {
#pragma unroll
        for (int kl = 0; kl < 16; kl++)
            As[lm][lcol][kl] = f2tf(Asrc[(size_t)(k0 + kl) * 512 + n0 + lcol]);
#pragma unroll
        for (int i = 0; i < 4; i++) {
            int idx = i * 256 + tid;
            int kl = idx >> 6, c = idx & 63;
            Bs[c][kl] = f2tf(Xb[(k0 + kl) * 64 + c]);
        }
        __syncthreads();
#pragma unroll
        for (int kk = 0; kk < 16; kk += 8) {
            uint2 al[2], ah[2];
#pragma unroll
            for (int m = 0; m < 2; m++) {
                al[m] = *(uint2*)&As[mat][nw + m * 16 + g][kk + 2 * t];
                ah[m] = *(uint2*)&As[mat][nw + m * 16 + 8 + g][kk + 2 * t];
            }
#pragma unroll
            for (int nt = 0; nt < 8; nt++) {
                uint2 b = *(uint2*)&Bs[nt * 8 + g][kk + 2 * t];
#pragma unroll
                for (int m = 0; m < 2; m++)
                    mma_tf32(acc[m][nt], al[m].x, ah[m].x, al[m].y, ah[m].y,
                             b.x, b.y);
            }
        }
        __syncthreads();
    }
#pragma unroll
    for (int m = 0; m < 2; m++) {
        int row = n0 + nw + m * 16 + g;
#pragma unroll
        for (int nt = 0; nt < 8; nt++) {
            int col = nt * 8 + 2 * t;
            *(float2*)&Yb[(size_t)row * 64 + col] =
                make_float2(acc[m][nt].x, acc[m][nt].y);
            *(float2*)&Yb[(size_t)(row + 8) * 64 + col] =
                make_float2(acc[m][nt].z, acc[m][nt].w);
        }
    }
}

// ---------------------------------------------------------------------------
// gcn1 (tf32): out = Xcat(128x192) @ W1[bh](192x128) + b1 -> sigmoid ->
// zde (cols 0-63, warps 0-3) and rg (cols 64-127, warps 4-7).
// grid (4, 768), 256 threads. Warp tile 32(m) x 64(n).
// ---------------------------------------------------------------------------
__global__ __launch_bounds__(256) void k_gcn1t() {
    int bh = blockIdx.y;
    int n0 = blockIdx.x * 128;
    const float* deb = g_de + (size_t)bh * 32768;
    const float* y1b = g_Y1 + (size_t)bh * 32768;
    const float* y2b = g_Y2 + (size_t)bh * 32768;
    const float* Wb = g_W1 + (size_t)bh * 24960;
    const float* bvp = g_b1 + bh * 128;
    __shared__ uint32_t As[128][20];
    __shared__ uint32_t Bs[128][20];
    int tid = threadIdx.x;
    int warp = tid >> 5, lane = tid & 31;
    int wm = warp & 3, wn = warp >> 2;
    int g = lane >> 2, t = lane & 3;
    float4 acc[2][8];
#pragma unroll
    for (int m = 0; m < 2; m++)
#pragma unroll
        for (int nt = 0; nt < 8; nt++)
            acc[m][nt] = make_float4(0.f, 0.f, 0.f, 0.f);

    for (int kc = 0; kc < 12; kc++) {
        int r0 = kc * 16, src = r0 >> 6, c0 = r0 & 63;
#pragma unroll
        for (int i = 0; i < 2; i++) {
            int idx = i * 1024 + tid * 4;
            int row = idx >> 4, kl = idx & 15;
            size_t gofs = (size_t)(n0 + row) * 64 + c0 + kl;
            float4 v;
            if (src == 0) v = *(const float4*)&deb[gofs];
            else if (src == 1) v = *(const float4*)&y1b[gofs];
            else {
                float4 a2 = *(const float4*)&y2b[gofs];
                float4 dd = *(const float4*)&deb[gofs];
                v = make_float4(2.f * a2.x - dd.x, 2.f * a2.y - dd.y,
                                2.f * a2.z - dd.z, 2.f * a2.w - dd.w);
            }
            As[row][kl + 0] = f2tf(v.x); As[row][kl + 1] = f2tf(v.y);
            As[row][kl + 2] = f2tf(v.z); As[row][kl + 3] = f2tf(v.w);
        }
#pragma unroll
        for (int i = 0; i < 2; i++) {
            int idx = i * 1024 + tid * 4;
            int kl = idx >> 7, o = idx & 127;
            int r = r0 + kl;
            int gr = r + (r >> 6) + 1;    // skip zero i=0 channel per 65-block
            float4 v = *(const float4*)&Wb[gr * 128 + o];
            Bs[o + 0][kl] = f2tf(v.x); Bs[o + 1][kl] = f2tf(v.y);
            Bs[o + 2][kl] = f2tf(v.z); Bs[o + 3][kl] = f2tf(v.w);
        }
        __syncthreads();
#pragma unroll
        for (int kk = 0; kk < 16; kk += 8) {
            uint2 al[2], ah[2];
#pragma unroll
            for (int m = 0; m < 2; m++) {
                al[m] = *(uint2*)&As[wm * 32 + m * 16 + g][kk + 2 * t];
                ah[m] = *(uint2*)&As[wm * 32 + m * 16 + 8 + g][kk + 2 * t];
            }
#pragma unroll
            for (int nt = 0; nt < 8; nt++) {
                uint2 b = *(uint2*)&Bs[wn * 64 + nt * 8 + g][kk + 2 * t];
#pragma unroll
                for (int m = 0; m < 2; m++)
                    mma_tf32(acc[m][nt], al[m].x, ah[m].x, al[m].y, ah[m].y,
                             b.x, b.y);
            }
        }
        __syncthreads();
    }
    float* zdeb = g_zde + (size_t)bh * 32768;
    float* rgb = g_rg + (size_t)bh * 32768;
#pragma unroll
    for (int m = 0; m < 2; m++) {
#pragma unroll
        for (int nt = 0; nt < 8; nt++) {
            int col = wn * 64 + nt * 8 + 2 * t;
            float bc0 = bvp[col], bc1 = bvp[col + 1];
#pragma unroll
            for (int half = 0; half < 2; half++) {
                int row = n0 + wm * 32 + m * 16 + half * 8 + g;
                float v0 = (half ? acc[m][nt].z : acc[m][nt].x) + bc0;
                float v1 = (half ? acc[m][nt].w : acc[m][nt].y) + bc1;
                float s0 = 1.f / (1.f + expf(-v0));
                float s1 = 1.f / (1.f + expf(-v1));
                if (wn == 0) {
                    zdeb[(size_t)row * 64 + col]     = s0 * deb[(size_t)row * 64 + col];
                    zdeb[(size_t)row * 64 + col + 1] = s1 * deb[(size_t)row * 64 + col + 1];
                } else {
                    rgb[(size_t)row * 64 + (col - 64)]     = s0;
                    rgb[(size_t)row * 64 + (col - 64) + 1] = s1;
                }
            }
        }
    }
}

// ---------------------------------------------------------------------------
// gcn2 (tf32) + GRU combine + output projection.  Xcat from (zde, Y1, Y2).
// grid (4, 768), 128 threads (4 warps, all in m). Warp tile 32 x 64, K=192.
// ---------------------------------------------------------------------------
__global__ __launch_bounds__(128) void k_gcn2t(float* __restrict__ out,
                                               const float* __restrict__ ow,
                                               const float* __restrict__ ob) {
    int bh = blockIdx.y;
    int tt = bh % 12;
    int n0 = blockIdx.x * 128;
    const float* xb  = g_zde + (size_t)bh * 32768;
    const float* y1b = g_Y1 + (size_t)bh * 32768;
    const float* y2b = g_Y2 + (size_t)bh * 32768;
    const float* deb = g_de + (size_t)bh * 32768;
    const float* rgb = g_rg + (size_t)bh * 32768;
    const float* Wb = g_W2 + (size_t)bh * 12480;
    const float* bvp = g_b2 + bh * 64;
    __shared__ uint32_t As[128][20];
    __shared__ uint32_t Bs[64][20];
    int tid = threadIdx.x;
    int warp = tid >> 5, lane = tid & 31;
    int g = lane >> 2, t = lane & 3;
    int nw = warp * 32;
    float4 acc[2][8];
#pragma unroll
    for (int m = 0; m < 2; m++)
#pragma unroll
        for (int nt = 0; nt < 8; nt++)
            acc[m][nt] = make_float4(0.f, 0.f, 0.f, 0.f);

    for (int kc = 0; kc < 12; kc++) {
        int r0 = kc * 16, src = r0 >> 6, c0 = r0 & 63;
#pragma unroll
        for (int i = 0; i < 4; i++) {
            int idx = i * 512 + tid * 4;
            int row = idx >> 4, kl = idx & 15;
            size_t gofs = (size_t)(n0 + row) * 64 + c0 + kl;
            float4 v;
            if (src == 0) v = *(const float4*)&xb[gofs];
            else if (src == 1) v = *(const float4*)&y1b[gofs];
            else {
                float4 a2 = *(const float4*)&y2b[gofs];
                float4 dd = *(const float4*)&xb[gofs];
                v = make_float4(2.f * a2.x - dd.x, 2.f * a2.y - dd.y,
                                2.f * a2.z - dd.z, 2.f * a2.w - dd.w);
            }
            As[row][kl + 0] = f2tf(v.x); As[row][kl + 1] = f2tf(v.y);
            As[row][kl + 2] = f2tf(v.z); As[row][kl + 3] = f2tf(v.w);
        }
#pragma unroll
        for (int i = 0; i < 2; i++) {
            int idx = i * 512 + tid * 4;
            int kl = idx >> 6, o = idx & 63;
            int r = r0 + kl;
            int gr = r + (r >> 6) + 1;
            float4 v = *(const float4*)&Wb[gr * 64 + o];
            Bs[o + 0][kl] = f2tf(v.x); Bs[o + 1][kl] = f2tf(v.y);
            Bs[o + 2][kl] = f2tf(v.z); Bs[o + 3][kl] = f2tf(v.w);
        }
        __syncthreads();
#pragma unroll
        for (int kk = 0; kk < 16; kk += 8) {
            uint2 al[2], ah[2];
#pragma unroll
            for (int m = 0; m < 2; m++) {
                al[m] = *(uint2*)&As[nw + m * 16 + g][kk + 2 * t];
                ah[m] = *(uint2*)&As[nw + m * 16 + 8 + g][kk + 2 * t];
            }
#pragma unroll
            for (int nt = 0; nt < 8; nt++) {
                uint2 b = *(uint2*)&Bs[nt * 8 + g][kk + 2 * t];
#pragma unroll
                for (int m = 0; m < 2; m++)
                    mma_tf32(acc[m][nt], al[m].x, ah[m].x, al[m].y, ah[m].y,
                             b.x, b.y);
            }
        }
        __syncthreads();
    }
    // epilogue: tanh -> GRU -> out-projection (reduce 64 cols per row)
#pragma unroll
    for (int m = 0; m < 2; m++) {
        float sum0 = 0.f, sum1 = 0.f;   // rows m*16+g and m*16+8+g
        int rbase = n0 + nw + m * 16 + g;
#pragma unroll
        for (int nt = 0; nt < 8; nt++) {
            int col = nt * 8 + 2 * t;
            float b0 = bvp[col], b1 = bvp[col + 1];
            float w0 = ow[tt * 64 + col], w1 = ow[tt * 64 + col + 1];
            {
                int row = rbase;
                float gv0 = tanhf(acc[m][nt].x + b0);
                float gv1 = tanhf(acc[m][nt].y + b1);
                float r0v = rgb[(size_t)row * 64 + col];
                float r1v = rgb[(size_t)row * 64 + col + 1];
                float st0 = r0v * deb[(size_t)row * 64 + col] + (1.f - r0v) * gv0;
                float st1 = r1v * deb[(size_t)row * 64 + col + 1] + (1.f - r1v) * gv1;
                sum0 = fmaf(st0, w0, sum0); sum0 = fmaf(st1, w1, sum0);
            }
            {
                int row = rbase + 8;
                float gv0 = tanhf(acc[m][nt].z + b0);
                float gv1 = tanhf(acc[m][nt].w + b1);
                float r0v = rgb[(size_t)row * 64 + col];
                float r1v = rgb[(size_t)row * 64 + col + 1];
                float st0 = r0v * deb[(size_t)row * 64 + col] + (1.f - r0v) * gv0;
                float st1 = r1v * deb[(size_t)row * 64 + col + 1] + (1.f - r1v) * gv1;
                sum1 = fmaf(st0, w0, sum1); sum1 = fmaf(st1, w1, sum1);
            }
        }
        sum0 += __shfl_xor_sync(0xffffffffu, sum0, 1);
        sum0 += __shfl_xor_sync(0xffffffffu, sum0, 2);
        sum1 += __shfl_xor_sync(0xffffffffu, sum1, 1);
        sum1 += __shfl_xor_sync(0xffffffffu, sum1, 2);
        if (t == 0) {
            out[(size_t)bh * 512 + rbase]     = sum0 + ob[tt];
            out[(size_t)bh * 512 + rbase + 8] = sum1 + ob[tt];
        }
    }
}

// ---------------------------------------------------------------------------
extern "C" void kernel_launch(void* const* d_in, const int* in_sizes, int n_in,
                              void* d_out, int out_size) {
    (void)in_sizes; (void)n_in; (void)out_size;
    const float* hN  = (const float*)d_in[2];
    const float* ne1 = (const float*)d_in[3];
    const float* ne2 = (const float*)d_in[4];
    const float* E   = (const float*)d_in[5];
    const float* Wq  = (const float*)d_in[6];
    const float* bq  = (const float*)d_in[7];
    const float* Wk  = (const float*)d_in[8];
    const float* bk  = (const float*)d_in[9];
    const float* Wv  = (const float*)d_in[10];
    const float* bv  = (const float*)d_in[11];
    const float* taw = (const float*)d_in[12];
    const float* tab = (const float*)d_in[13];
    const float* gwp = (const float*)d_in[14];
    const float* gw  = (const float*)d_in[15];
    const float* gbp = (const float*)d_in[16];
    const float* gb  = (const float*)d_in[17];
    const float* uwp = (const float*)d_in[18];
    const float* uw  = (const float*)d_in[19];
    const float* ubp = (const float*)d_in[20];
    const float* ub  = (const float*)d_in[21];
    const float* ow  = (const float*)d_in[22];
    const float* ob  = (const float*)d_in[23];
    float* out = (float*)d_out;

    k_At<<<512, 128>>>(E);
    k_A2<<<dim3(4, 4), 256>>>();
    k_wmix<<<dim3(98, 48), 256>>>(ne2, gwp, gw, 4, 24960);
    k_wmix<<<dim3(49, 48), 256>>>(ne2, uwp, uw, 5, 12480);
    k_wmix<<<dim3(1, 48), 256>>>(ne2, gbp, gb, 6, 128);
    k_wmix<<<dim3(1, 48), 256>>>(ne2, ubp, ub, 7, 64);
    k_qs<<<768, 64>>>(ne2, Wq, bq);
    k_kpvp<<<64, 128>>>(ne1, Wk, bk, Wv, bv);
    k_attn<<<dim3(128, 64), dim3(64, 4)>>>(hN, Wq, Wk, Wv, taw, tab);

    k_gAx2<<<dim3(4, 768), 256>>>(0);    // Y1 = A@de, Y2 = A2@de
    k_gcn1t<<<dim3(4, 768), 256>>>();    // -> rg, zde
    k_gAx2<<<dim3(4, 768), 256>>>(3);    // Y1 = A@zde, Y2 = A2@zde
    k_gcn2t<<<dim3(4, 768), 128>>>(out, ow, ob);
}